// round 17
// baseline (speedup 1.0000x reference)
#include <cuda_runtime.h>
#include <cuda_fp16.h>
#include <cstdint>

#define N      4096
#define IN_F   128
#define OUT_F  64
#define H      4
#define C      (H * OUT_F)   // 256
#define NEG    0.2f
#define MAXE_W 96            // per-node cap; max degree ~67+self

// Scratch (allocation-free rule: device globals). 16B-aligned for vector access.
__device__ __align__(16) __half g_hh[N * C];   // 2 MB: h in fp16
__device__ __align__(16) float  g_src[N * H];
__device__ __align__(16) float  g_tgt[N * H];

// packed fp32x2 helpers (Blackwell)
typedef unsigned long long u64;
__device__ __forceinline__ void fma_f32x2(u64& acc, u64 a, u64 b) {
    asm("fma.rn.f32x2 %0, %1, %2, %0;" : "+l"(acc) : "l"(a), "l"(b));
}
__device__ __forceinline__ u64 pack2(float lo, float hi) {
    u64 r; asm("mov.b64 %0, {%1, %2};" : "=l"(r) : "f"(lo), "f"(hi)); return r;
}
__device__ __forceinline__ float2 unpack2(u64 v) {
    float2 f; asm("mov.b64 {%0, %1}, %2;" : "=f"(f.x), "=f"(f.y) : "l"(v)); return f;
}

// movemask for float4 of {0.0f, 1.0f}: nonzero <=> byte3 != 0
__device__ __forceinline__ unsigned movemask4(float4 v) {
    const uint4 u = *reinterpret_cast<const uint4*>(&v);
    const unsigned pA = __byte_perm(u.x, u.y, 0x7373);
    const unsigned pB = __byte_perm(u.z, u.w, 0x7373);
    const unsigned pC = __byte_perm(pA, pB, 0x5410);
    return ((pC & 0x01010101u) * 0x01020408u) >> 24;
}

// tf32 helpers
__device__ __forceinline__ uint32_t f2tf32(float f) {
    uint32_t u; asm("cvt.rna.tf32.f32 %0, %1;" : "=r"(u) : "f"(f)); return u;
}
__device__ __forceinline__ void mma_tf32(float* d, const uint32_t* A,
                                         uint32_t b0, uint32_t b1) {
    asm("mma.sync.aligned.m16n8k8.row.col.f32.tf32.tf32.f32 "
        "{%0,%1,%2,%3}, {%4,%5,%6,%7}, {%8,%9}, {%0,%1,%2,%3};"
        : "+f"(d[0]), "+f"(d[1]), "+f"(d[2]), "+f"(d[3])
        : "r"(A[0]), "r"(A[1]), "r"(A[2]), "r"(A[3]), "r"(b0), "r"(b1));
}

// ---------------------------------------------------------------------------
// K1: h = x @ W via tf32 tensor cores. Operands converted to tf32 ONCE during
// smem staging (inner loop = pure LDS + MMA). Fragment layout validated in R16.
// CTA 128 thr, tile 64(M)x64(N) = one head for 64 rows; K in two 64-chunks.
// ---------------------------------------------------------------------------
#define GM 64
#define GN 64
#define GK 64
__global__ __launch_bounds__(128)
void k1_mma(const float* __restrict__ x, const float* __restrict__ W,
            const float* __restrict__ a) {
    __shared__ __align__(16) uint32_t xs[GM][GK + 4];   // tf32 bits
    __shared__ __align__(16) uint32_t ws[GK][GN + 4];

    const int n0 = blockIdx.x * GM;
    const int c0 = blockIdx.y * GN;
    const int hd = blockIdx.y;
    const int t    = threadIdx.x;       // 128
    const int warp = t >> 5;            // rows warp*16 .. warp*16+15
    const int lane = t & 31;
    const int g    = lane >> 2;         // 0..7
    const int tg   = lane & 3;          // 0..3

    float d[8][4];
#pragma unroll
    for (int n8 = 0; n8 < 8; n8++)
#pragma unroll
        for (int r = 0; r < 4; r++) d[n8][r] = 0.f;

    for (int kc = 0; kc < IN_F; kc += GK) {
        // stage + convert to tf32: 8 float4 each per thread
#pragma unroll
        for (int jj = 0; jj < 8; jj++) {
            const int idx = t + jj * 128;
            const int m = idx >> 4, q = idx & 15;
            const float4 v = *(const float4*)(x + (size_t)(n0 + m) * IN_F + kc + q * 4);
            uint4 u;
            u.x = f2tf32(v.x); u.y = f2tf32(v.y);
            u.z = f2tf32(v.z); u.w = f2tf32(v.w);
            *(uint4*)&xs[m][q * 4] = u;
        }
#pragma unroll
        for (int jj = 0; jj < 8; jj++) {
            const int idx = t + jj * 128;
            const int k = idx >> 4, q = idx & 15;
            const float4 v = *(const float4*)(W + (size_t)(kc + k) * C + c0 + q * 4);
            uint4 u;
            u.x = f2tf32(v.x); u.y = f2tf32(v.y);
            u.z = f2tf32(v.z); u.w = f2tf32(v.w);
            *(uint4*)&ws[k][q * 4] = u;
        }
        __syncthreads();

#pragma unroll
        for (int ks = 0; ks < GK / 8; ks++) {
            const int k0 = ks * 8;
            uint32_t A[4];
            A[0] = xs[warp * 16 + g    ][k0 + tg    ];
            A[1] = xs[warp * 16 + g + 8][k0 + tg    ];
            A[2] = xs[warp * 16 + g    ][k0 + tg + 4];
            A[3] = xs[warp * 16 + g + 8][k0 + tg + 4];
#pragma unroll
            for (int n8 = 0; n8 < 8; n8++) {
                const uint32_t b0 = ws[k0 + tg    ][n8 * 8 + g];
                const uint32_t b1 = ws[k0 + tg + 4][n8 * 8 + g];
                mma_tf32(d[n8], A, b0, b1);
            }
        }
        __syncthreads();
    }

    // --- epilogue: h -> fp16 + fused src/tgt (layout validated in R16)
    const int row_a = n0 + warp * 16 + g;
    const int row_b = row_a + 8;

    float sA = 0.f, tA = 0.f, sB = 0.f, tB = 0.f;
#pragma unroll
    for (int n8 = 0; n8 < 8; n8++) {
        const int cl = n8 * 8 + 2 * tg;
        *(__half2*)&g_hh[(size_t)row_a * C + c0 + cl] =
            __floats2half2_rn(d[n8][0], d[n8][1]);
        *(__half2*)&g_hh[(size_t)row_b * C + c0 + cl] =
            __floats2half2_rn(d[n8][2], d[n8][3]);
        const float2 as2 = *(const float2*)(a + hd * 2 * OUT_F + cl);
        const float2 at2 = *(const float2*)(a + hd * 2 * OUT_F + OUT_F + cl);
        sA += d[n8][0] * as2.x + d[n8][1] * as2.y;
        tA += d[n8][0] * at2.x + d[n8][1] * at2.y;
        sB += d[n8][2] * as2.x + d[n8][3] * as2.y;
        tB += d[n8][2] * at2.x + d[n8][3] * at2.y;
    }
#pragma unroll
    for (int off = 1; off <= 2; off <<= 1) {
        sA += __shfl_xor_sync(0xFFFFFFFFu, sA, off);
        tA += __shfl_xor_sync(0xFFFFFFFFu, tA, off);
        sB += __shfl_xor_sync(0xFFFFFFFFu, sB, off);
        tB += __shfl_xor_sync(0xFFFFFFFFu, tB, off);
    }
    if (tg == 0) {
        g_src[row_a * H + hd] = sA;
        g_tgt[row_a * H + hd] = tA;
        g_src[row_b * H + hd] = sB;
        g_tgt[row_b * H + hd] = tB;
    }
}

// ---------------------------------------------------------------------------
// K3: WARP-per-node, weights FUSED into the gather loop.
// Per edge: 4B broadcast g_tgt load -> leaky -> exp -> wsum += w; then the
// uint4 h-row load and 4 f32x2 FMAs. Normalize by 1/wsum at the end (all
// lanes of a head-group compute identical wsum -> no reduction, no s_w smem,
// no separate weight pass, no block/warp barriers beyond one syncwarp).
// ---------------------------------------------------------------------------
__global__ __launch_bounds__(256)
void k3_gat(const float* __restrict__ adj, float* __restrict__ out) {
    const int t    = threadIdx.x;
    const int warp = t >> 5;
    const int lane = t & 31;
    const int i    = blockIdx.x * 8 + warp;

    __shared__ __align__(16) int s_idx[8][MAXE_W];        // 3 KB only

    // --- phase 1: adj row -> 128-bit movemask per lane
    const float4* arow = reinterpret_cast<const float4*>(adj + (size_t)i * N);
    unsigned m[4];
#pragma unroll
    for (int w = 0; w < 4; w++) {
        float4 v[8];
#pragma unroll
        for (int k8 = 0; k8 < 8; k8++)
            v[k8] = __ldcs(arow + lane + 32 * (w * 8 + k8));
        unsigned mw = 0;
#pragma unroll
        for (int k8 = 0; k8 < 8; k8++)
            mw |= movemask4(v[k8]) << (k8 * 4);
        m[w] = mw;
    }

    // self-bit from owner lane's mask
    const int f_i   = i >> 2;
    const int owner = f_i & 31;
    const int k_i   = f_i >> 5;
    const int wsel  = k_i >> 3;
    const unsigned mw_i = (wsel == 0) ? m[0] : (wsel == 1) ? m[1] : (wsel == 2) ? m[2] : m[3];
    const int selfp = (int)((mw_i >> (((k_i & 7) << 2) | (i & 3))) & 1u);
    const int self  = 1 - __shfl_sync(0xFFFFFFFFu, selfp, owner);

    // --- scan + emit
    const int myc = __popc(m[0]) + __popc(m[1]) + __popc(m[2]) + __popc(m[3]);
    int sc = myc;
#pragma unroll
    for (int off = 1; off < 32; off <<= 1) {
        const int nv = __shfl_up_sync(0xFFFFFFFFu, sc, off);
        if (lane >= off) sc += nv;
    }
    const int cnt = __shfl_sync(0xFFFFFFFFu, sc, 31);
    const int cnt_full = cnt + self;

    int p = sc - myc;
#pragma unroll
    for (int w = 0; w < 4; w++) {
        unsigned mm = m[w];
        while (mm) {
            const int b = __ffs(mm) - 1;
            mm &= mm - 1;
            const int k = w * 8 + (b >> 2);
            s_idx[warp][p++] = ((lane + 32 * k) << 2) | (b & 3);
        }
    }
    if (self && lane == 0) s_idx[warp][cnt] = i;   // append self-edge
    __syncwarp();

    // --- phase 2: fused gather + weights
    const int ghd = lane >> 3;                     // head of this lane's 8 feats
    const float sv_g = g_src[i * H + ghd];         // broadcast within head group
    const char* hbase = (const char*)g_hh + lane * 16;
    const float* tgt_h = g_tgt + ghd;

    u64 accp[4] = {0ull, 0ull, 0ull, 0ull};
    float wsum = 0.f;

    int e = 0;
    for (; e + 3 < cnt_full; e += 4) {
        int   jj[4];
        float tv[4];
        uint4 uu[4];
#pragma unroll
        for (int u = 0; u < 4; u++) jj[u] = s_idx[warp][e + u];
#pragma unroll
        for (int u = 0; u < 4; u++) tv[u] = __ldg(tgt_h + jj[u] * H);
#pragma unroll
        for (int u = 0; u < 4; u++)
            uu[u] = *(const uint4*)(hbase + (size_t)jj[u] * 512);
#pragma unroll
        for (int u = 0; u < 4; u++) {
            float ev = sv_g + tv[u];
            ev = (ev > 0.f) ? ev : NEG * ev;
            const float w = __expf(ev);
            wsum += w;
            const u64 wp = pack2(w, w);
            const __half2* hp = (const __half2*)&uu[u];
#pragma unroll
            for (int s = 0; s < 4; s++) {
                const float2 f = __half22float2(hp[s]);
                fma_f32x2(accp[s], pack2(f.x, f.y), wp);
            }
        }
    }
    for (; e < cnt_full; e++) {
        const int   j = s_idx[warp][e];
        const float tv = __ldg(tgt_h + j * H);
        float ev = sv_g + tv;
        ev = (ev > 0.f) ? ev : NEG * ev;
        const float w = __expf(ev);
        wsum += w;
        const u64 wp = pack2(w, w);
        const uint4 u = *(const uint4*)(hbase + (size_t)j * 512);
        const __half2* hp = (const __half2*)&u;
#pragma unroll
        for (int s = 0; s < 4; s++) {
            const float2 f = __half22float2(hp[s]);
            fma_f32x2(accp[s], pack2(f.x, f.y), wp);
        }
    }

    // --- normalize + direct store (no reduction: wsum identical within group)
    const float inv = 1.f / wsum;
    const float2 a0 = unpack2(accp[0]), a1 = unpack2(accp[1]);
    const float2 a2 = unpack2(accp[2]), a3 = unpack2(accp[3]);
    float* op = out + (size_t)i * C + lane * 8;
    *(float4*)op       = make_float4(a0.x * inv, a0.y * inv, a1.x * inv, a1.y * inv);
    *(float4*)(op + 4) = make_float4(a2.x * inv, a2.y * inv, a3.x * inv, a3.y * inv);
}

// ---------------------------------------------------------------------------
extern "C" void kernel_launch(void* const* d_in, const int* in_sizes, int n_in,
                              void* d_out, int out_size) {
    const float* x   = (const float*)d_in[0];
    const float* adj = (const float*)d_in[1];
    const float* W   = (const float*)d_in[2];
    const float* a   = (const float*)d_in[3];
    float* out = (float*)d_out;

    dim3 g1(N / GM, C / GN);            // 64 x 4 = 256 CTAs
    k1_mma<<<g1, 128>>>(x, W, a);
    k3_gat<<<N / 8, 256>>>(adj, out);   // warp-per-node
}